// round 16
// baseline (speedup 1.0000x reference)
#include <cuda_runtime.h>
#include <cuda_fp16.h>
#include <cstdint>
#include <cstddef>

#define NN 50000
#define NE 800000
#define DI 256
#define DO 256
#define NR 8

#define NB (NN * NR)                  // 400000 (row,rel) buckets
#define SB1 512
#define NBLK2 ((NB + SB1 - 1) / SB1)  // 782 scan blocks

// fp16 copies of x and W
__device__ __half g_xh[(size_t)NN * DI];      // 25.6 MB (L2-resident)
__device__ __half g_wh[(size_t)NR * DI * DO]; // 1 MB
// CSR-by-(row,rel) scaffolding
__device__ int g_cnt[NB];
__device__ int g_offs[NB + 1];
__device__ int g_curs[NB];
__device__ int g_bsum[NBLK2];
__device__ int g_bbase[NBLK2];
__device__ int g_perm[NE];            // col per slot

__device__ __forceinline__ void cp_async16(uint32_t saddr, const void* gaddr) {
    asm volatile("cp.async.cg.shared.global [%0], [%1], 16;" :: "r"(saddr), "l"(gaddr));
}
__device__ __forceinline__ uint32_t smem_u32(const void* p) {
    uint32_t a;
    asm("{ .reg .u64 t; cvta.to.shared.u64 t, %1; cvt.u32.u64 %0, t; }" : "=r"(a) : "l"(p));
    return a;
}
__device__ __forceinline__ void ldsm_x4(uint32_t* r, uint32_t addr) {
    asm volatile("ldmatrix.sync.aligned.m8n8.x4.shared.b16 {%0,%1,%2,%3}, [%4];"
                 : "=r"(r[0]), "=r"(r[1]), "=r"(r[2]), "=r"(r[3]) : "r"(addr));
}
__device__ __forceinline__ void ldsm_x4_t(uint32_t* r, uint32_t addr) {
    asm volatile("ldmatrix.sync.aligned.m8n8.x4.trans.shared.b16 {%0,%1,%2,%3}, [%4];"
                 : "=r"(r[0]), "=r"(r[1]), "=r"(r[2]), "=r"(r[3]) : "r"(addr));
}

// ---------------------------------------------------------------------------
// fp32 -> fp16 convert
// ---------------------------------------------------------------------------
__global__ void rgcn_tohalf(const float4* __restrict__ src, half2* __restrict__ dst, int n4) {
    int i = blockIdx.x * blockDim.x + threadIdx.x;
    if (i >= n4) return;
    float4 v = src[i];
    dst[2 * i]     = __floats2half2_rn(v.x, v.y);
    dst[2 * i + 1] = __floats2half2_rn(v.z, v.w);
}

// ---------------------------------------------------------------------------
// CSR by (row,rel): count -> 3-phase scan -> fill
// ---------------------------------------------------------------------------
__global__ void rgcn_count(const int* __restrict__ edge_index,
                           const int* __restrict__ edge_type, int* __restrict__ cnt) {
    int e = blockIdx.x * blockDim.x + threadIdx.x;
    if (e < NE) atomicAdd(&cnt[edge_index[e] * NR + edge_type[e]], 1);
}

__global__ __launch_bounds__(SB1)
void rgcn_scanA(const int* __restrict__ cnt, int* __restrict__ offs, int* __restrict__ bsum) {
    __shared__ int s[SB1];
    const int t = threadIdx.x;
    const int i = blockIdx.x * SB1 + t;
    int v = (i < NB) ? cnt[i] : 0;
    s[t] = v;
    __syncthreads();
#pragma unroll
    for (int d = 1; d < SB1; d <<= 1) {
        int u = (t >= d) ? s[t - d] : 0;
        __syncthreads();
        s[t] += u;
        __syncthreads();
    }
    if (i < NB) offs[i] = s[t] - v;
    if (t == SB1 - 1) bsum[blockIdx.x] = s[SB1 - 1];
}

__global__ __launch_bounds__(1024)
void rgcn_scanB(const int* __restrict__ bsum, int* __restrict__ bbase) {
    __shared__ int s[1024];
    const int t = threadIdx.x;
    int v = (t < NBLK2) ? bsum[t] : 0;
    s[t] = v;
    __syncthreads();
#pragma unroll
    for (int d = 1; d < 1024; d <<= 1) {
        int u = (t >= d) ? s[t - d] : 0;
        __syncthreads();
        s[t] += u;
        __syncthreads();
    }
    if (t < NBLK2) bbase[t] = s[t] - v;
}

__global__ __launch_bounds__(SB1)
void rgcn_scanC(int* __restrict__ offs, const int* __restrict__ bbase,
                int* __restrict__ curs) {
    const int i = blockIdx.x * SB1 + threadIdx.x;
    if (i >= NB) return;
    int o = offs[i] + bbase[blockIdx.x];
    offs[i] = o;
    curs[i] = o;
    if (i == 0) offs[NB] = NE;
}

__global__ void rgcn_fill(const int* __restrict__ edge_index,
                          const int* __restrict__ edge_type,
                          int* __restrict__ curs, int* __restrict__ perm) {
    int e = blockIdx.x * blockDim.x + threadIdx.x;
    if (e >= NE) return;
    int pos = atomicAdd(&curs[edge_index[e] * NR + edge_type[e]], 1);
    perm[pos] = edge_index[NE + e];
}

// ---------------------------------------------------------------------------
// FUSED kernel: per 128-row m-tile, for each relation r:
//   (1) gather-accumulate A_r[128][256] fp16 into SMEM (xh is L2-resident)
//   (2) MMA A_r @ W[r] over 4 k16x4 chunks, B streamed via 2-stage cp.async
// Persistent fp32 accumulators across relations; epilogue bias+relu -> out.
// 256 threads (8 warps, 2m x 4n), warp tile 64x64, full N=256, 1 CTA/SM.
// ---------------------------------------------------------------------------
#define BK 64
#define NSTEP (NR * (DI / BK))        // 32
#define APH2 264                      // A pitch (halves), conflict-free class
#define BPH2 264                      // B pitch (halves)
#define A_SM_BYTES (128 * APH2 * 2)   // 67584
#define B_STAGE_BYTES (BK * BPH2 * 2) // 33792
#define SMEM_DYN (A_SM_BYTES + 2 * B_STAGE_BYTES)  // 135168

__global__ __launch_bounds__(256, 1)
void rgcn_fused(const __half* __restrict__ xh, const __half* __restrict__ w,
                const float* __restrict__ bias,
                const int* __restrict__ offs, const int* __restrict__ perm,
                float* __restrict__ out) {
    extern __shared__ char smem[];

    const int m0 = blockIdx.x * 128;
    const int tid  = threadIdx.x;
    const int lane = tid & 31;
    const int wid  = tid >> 5;
    const int wm   = wid & 1;     // 2 m-halves of 64
    const int wn   = wid >> 1;    // 4 n-quarters of 64
    const int g    = lane >> 2;
    const int t    = lane & 3;

    const uint32_t sbase = smem_u32(smem);
    const uint32_t sA = sbase;
    const uint32_t sB = sbase + A_SM_BYTES;

    float c[4][8][4];
#pragma unroll
    for (int mi = 0; mi < 4; mi++)
#pragma unroll
        for (int ni = 0; ni < 8; ni++)
#pragma unroll
            for (int q = 0; q < 4; q++) c[mi][ni][q] = 0.0f;

    auto load_B = [&](int step, int stage) {
        const int r  = step >> 2;
        const int kt = (step & 3) * BK;
        const uint32_t dstB = sB + stage * B_STAGE_BYTES;
#pragma unroll
        for (int u = 0; u < 8; u++) {
            int v = tid + u * 256;            // 2048 lines = 64 rows x 32
            int row = v >> 5, c8 = v & 31;
            cp_async16(dstB + (row * BPH2 + c8 * 8) * 2,
                       w + (size_t)r * DI * DO + (size_t)(kt + row) * DO + c8 * 8);
        }
        asm volatile("cp.async.commit_group;" ::: "memory");
    };

    // gather A_r into SMEM: each warp owns 16 rows
    auto gather_A = [&](int r) {
#pragma unroll 1
        for (int i = 0; i < 16; i++) {
            const int lrow = wid * 16 + i;
            const int gm = m0 + lrow;
            float acc[8];
#pragma unroll
            for (int k = 0; k < 8; k++) acc[k] = 0.0f;
            if (gm < NN) {
                const int b = gm * NR + r;
                int j = offs[b];
                const int je = offs[b + 1];
                for (; j + 1 < je; j += 2) {
                    int c0 = perm[j], c1 = perm[j + 1];
                    uint4 v0 = __ldg((const uint4*)(xh + (size_t)c0 * DI) + lane);
                    uint4 v1 = __ldg((const uint4*)(xh + (size_t)c1 * DI) + lane);
                    float2 f;
                    f = __half22float2(*(const half2*)&v0.x); acc[0] += f.x; acc[1] += f.y;
                    f = __half22float2(*(const half2*)&v0.y); acc[2] += f.x; acc[3] += f.y;
                    f = __half22float2(*(const half2*)&v0.z); acc[4] += f.x; acc[5] += f.y;
                    f = __half22float2(*(const half2*)&v0.w); acc[6] += f.x; acc[7] += f.y;
                    f = __half22float2(*(const half2*)&v1.x); acc[0] += f.x; acc[1] += f.y;
                    f = __half22float2(*(const half2*)&v1.y); acc[2] += f.x; acc[3] += f.y;
                    f = __half22float2(*(const half2*)&v1.z); acc[4] += f.x; acc[5] += f.y;
                    f = __half22float2(*(const half2*)&v1.w); acc[6] += f.x; acc[7] += f.y;
                }
                if (j < je) {
                    int c0 = perm[j];
                    uint4 v0 = __ldg((const uint4*)(xh + (size_t)c0 * DI) + lane);
                    float2 f;
                    f = __half22float2(*(const half2*)&v0.x); acc[0] += f.x; acc[1] += f.y;
                    f = __half22float2(*(const half2*)&v0.y); acc[2] += f.x; acc[3] += f.y;
                    f = __half22float2(*(const half2*)&v0.z); acc[4] += f.x; acc[5] += f.y;
                    f = __half22float2(*(const half2*)&v0.w); acc[6] += f.x; acc[7] += f.y;
                }
            }
            uint32_t o[4];
            *(half2*)&o[0] = __floats2half2_rn(acc[0], acc[1]);
            *(half2*)&o[1] = __floats2half2_rn(acc[2], acc[3]);
            *(half2*)&o[2] = __floats2half2_rn(acc[4], acc[5]);
            *(half2*)&o[3] = __floats2half2_rn(acc[6], acc[7]);
            uint32_t dst = sA + (lrow * APH2 + lane * 8) * 2;
            asm volatile("st.shared.v4.b32 [%0], {%1,%2,%3,%4};"
                         :: "r"(dst), "r"(o[0]), "r"(o[1]), "r"(o[2]), "r"(o[3]) : "memory");
        }
    };

    const int a_row = wm * 64 + (lane & 15);
    const int a_kof = (lane >> 4) * 8;
    const int b_krow = (lane & 7) + ((lane >> 3) & 1) * 8;
    const int b_col  = wn * 64 + (lane >> 4) * 8;

    load_B(0, 0);

    for (int r = 0; r < NR; r++) {
        gather_A(r);
        __syncthreads();                       // A_r visible; prev MMA done

#pragma unroll
        for (int kc = 0; kc < 4; kc++) {
            const int step = r * 4 + kc;
            if (step + 1 < NSTEP) {
                load_B(step + 1, (step + 1) & 1);
                asm volatile("cp.async.wait_group 1;" ::: "memory");
            } else {
                asm volatile("cp.async.wait_group 0;" ::: "memory");
            }
            __syncthreads();                   // B stage ready

            const int kt = kc * BK;
            const uint32_t sBs = sB + (step & 1) * B_STAGE_BYTES;

#pragma unroll
            for (int ks = 0; ks < 4; ks++) {
                const int k16 = ks * 16;
                uint32_t a[4][4];
#pragma unroll
                for (int mi = 0; mi < 4; mi++)
                    ldsm_x4(a[mi], sA + ((a_row + mi * 16) * APH2 + kt + k16 + a_kof) * 2);
                uint32_t b[4][4];
#pragma unroll
                for (int p = 0; p < 4; p++)
                    ldsm_x4_t(b[p], sBs + ((k16 + b_krow) * BPH2 + b_col + p * 16) * 2);
#pragma unroll
                for (int p = 0; p < 4; p++) {
#pragma unroll
                    for (int mi = 0; mi < 4; mi++) {
                        asm volatile(
                            "mma.sync.aligned.m16n8k16.row.col.f32.f16.f16.f32 "
                            "{%0,%1,%2,%3}, {%4,%5,%6,%7}, {%8,%9}, {%0,%1,%2,%3};\n"
                            : "+f"(c[mi][2 * p][0]), "+f"(c[mi][2 * p][1]),
                              "+f"(c[mi][2 * p][2]), "+f"(c[mi][2 * p][3])
                            : "r"(a[mi][0]), "r"(a[mi][1]), "r"(a[mi][2]), "r"(a[mi][3]),
                              "r"(b[p][0]), "r"(b[p][1]));
                        asm volatile(
                            "mma.sync.aligned.m16n8k16.row.col.f32.f16.f16.f32 "
                            "{%0,%1,%2,%3}, {%4,%5,%6,%7}, {%8,%9}, {%0,%1,%2,%3};\n"
                            : "+f"(c[mi][2 * p + 1][0]), "+f"(c[mi][2 * p + 1][1]),
                              "+f"(c[mi][2 * p + 1][2]), "+f"(c[mi][2 * p + 1][3])
                            : "r"(a[mi][0]), "r"(a[mi][1]), "r"(a[mi][2]), "r"(a[mi][3]),
                              "r"(b[p][2]), "r"(b[p][3]));
                    }
                }
            }
            __syncthreads();                   // before overwriting B stage
        }
    }

    // epilogue: bias + relu -> fp32 out
    float2 bv[8];
#pragma unroll
    for (int ni = 0; ni < 8; ni++)
        bv[ni] = *(const float2*)(bias + wn * 64 + ni * 8 + t * 2);

#pragma unroll
    for (int mi = 0; mi < 4; mi++) {
#pragma unroll
        for (int ni = 0; ni < 8; ni++) {
            int row0 = m0 + wm * 64 + mi * 16 + g;
            int col  = wn * 64 + ni * 8 + t * 2;
            if (row0 < NN) {
                float2 o;
                o.x = fmaxf(c[mi][ni][0] + bv[ni].x, 0.f);
                o.y = fmaxf(c[mi][ni][1] + bv[ni].y, 0.f);
                *(float2*)(out + (size_t)row0 * DO + col) = o;
            }
            int row1 = row0 + 8;
            if (row1 < NN) {
                float2 o;
                o.x = fmaxf(c[mi][ni][2] + bv[ni].x, 0.f);
                o.y = fmaxf(c[mi][ni][3] + bv[ni].y, 0.f);
                *(float2*)(out + (size_t)row1 * DO + col) = o;
            }
        }
    }
}

extern "C" void kernel_launch(void* const* d_in, const int* in_sizes, int n_in,
                              void* d_out, int out_size) {
    const float* x          = (const float*)d_in[0];
    const int*   edge_index = (const int*)d_in[1];
    const int*   edge_type  = (const int*)d_in[2];
    const float* weight     = (const float*)d_in[3];
    const float* bias       = (const float*)d_in[4];
    float* out = (float*)d_out;

    __half *xh, *wh;
    int *cnt, *offs, *curs, *bsum, *bbase, *perm;
    cudaGetSymbolAddress((void**)&xh, g_xh);
    cudaGetSymbolAddress((void**)&wh, g_wh);
    cudaGetSymbolAddress((void**)&cnt, g_cnt);
    cudaGetSymbolAddress((void**)&offs, g_offs);
    cudaGetSymbolAddress((void**)&curs, g_curs);
    cudaGetSymbolAddress((void**)&bsum, g_bsum);
    cudaGetSymbolAddress((void**)&bbase, g_bbase);
    cudaGetSymbolAddress((void**)&perm, g_perm);

    cudaFuncSetAttribute(rgcn_fused, cudaFuncAttributeMaxDynamicSharedMemorySize, SMEM_DYN);

    // Fork: CSR build on s2, conversions on stream 0.
    cudaStream_t s2;
    cudaEvent_t evFork, evJoin;
    cudaStreamCreateWithFlags(&s2, cudaStreamNonBlocking);
    cudaEventCreateWithFlags(&evFork, cudaEventDisableTiming);
    cudaEventCreateWithFlags(&evJoin, cudaEventDisableTiming);

    cudaEventRecord(evFork, 0);
    cudaStreamWaitEvent(s2, evFork, 0);

    // Branch A: conversions
    const int xn4 = NN * DI / 4;
    const int wn4 = NR * DI * DO / 4;
    rgcn_tohalf<<<(xn4 + 255) / 256, 256>>>((const float4*)x, (half2*)xh, xn4);
    rgcn_tohalf<<<(wn4 + 255) / 256, 256>>>((const float4*)weight, (half2*)wh, wn4);

    // Branch B: CSR by (row,rel)
    cudaMemsetAsync(cnt, 0, NB * sizeof(int), s2);
    rgcn_count<<<(NE + 255) / 256, 256, 0, s2>>>(edge_index, edge_type, cnt);
    rgcn_scanA<<<NBLK2, SB1, 0, s2>>>(cnt, offs, bsum);
    rgcn_scanB<<<1, 1024, 0, s2>>>(bsum, bbase);
    rgcn_scanC<<<NBLK2, SB1, 0, s2>>>(offs, bbase, curs);
    rgcn_fill<<<(NE + 255) / 256, 256, 0, s2>>>(edge_index, edge_type, curs, perm);

    cudaEventRecord(evJoin, s2);
    cudaStreamWaitEvent(0, evJoin, 0);

    // Fused gather + GEMM + bias + relu
    rgcn_fused<<<(NN + 127) / 128, 256, SMEM_DYN>>>(xh, wh, bias, offs, perm, out);
}